// round 8
// baseline (speedup 1.0000x reference)
#include <cuda_runtime.h>
#include <cstdint>

#define B_  2
#define T_  4096
#define D_  768
#define H_  12
#define DK_ 64
#define M_  (B_*T_)   // 8192

// Scratch (allocation-free)
__device__ float g_Q[B_*H_*T_*DK_];
__device__ float g_K[B_*H_*T_*DK_];
__device__ float g_V[B_*H_*T_*DK_];
__device__ float g_O[M_*D_];

__device__ __forceinline__ uint32_t f2tf(float f) {
    uint32_t r; asm("cvt.rna.tf32.f32 %0, %1;" : "=r"(r) : "f"(f)); return r;
}
__device__ __forceinline__ float ex2f(float x) {
    float y; asm("ex2.approx.f32 %0, %1;" : "=f"(y) : "f"(x)); return y;
}
__device__ __forceinline__ void mma8(float* c, const uint32_t* a, const uint32_t* b) {
    asm volatile("mma.sync.aligned.m16n8k8.row.col.f32.tf32.tf32.f32 "
        "{%0,%1,%2,%3}, {%4,%5,%6,%7}, {%8,%9}, {%0,%1,%2,%3};"
        : "+f"(c[0]), "+f"(c[1]), "+f"(c[2]), "+f"(c[3])
        : "r"(a[0]), "r"(a[1]), "r"(a[2]), "r"(a[3]), "r"(b[0]), "r"(b[1]));
}
__device__ __forceinline__ void cpa16(uint32_t dst, const float* src) {
    asm volatile("cp.async.cg.shared.global [%0], [%1], 16;\n" :: "r"(dst), "l"(src));
}

// ===========================================================================
// GEMM: C[8192,768] = A @ W. Block 128x128, k-step 32, 256 thr, 8 warps
// (warp 64x32). cp.async double-buffered raw fp32; staging cvt pass; inner
// loop is pure LDS+HMMA. mode -1: z picks WQ/WK/WV -> split-head g_Q/K/V.
// mode 3: W0 -> row-major C. A==nullptr reads g_O.
// ===========================================================================
#define GSM_BYTES ((2*128*36 + 2*32*132) * 4)   // 70656

__global__ __launch_bounds__(256, 2) void gemm2(
        const float* __restrict__ A,
        const float* __restrict__ W0, const float* __restrict__ W1,
        const float* __restrict__ W2,
        float* __restrict__ C, int mode) {
    extern __shared__ float sg[];
    float* As = sg;                  // [2][128][36]
    float* Ws = sg + 2*128*36;       // [2][32][132]
    const float* Ar = A ? A : g_O;
    const int z = blockIdx.z;
    const float* W = (mode == 3) ? W0 : (z == 0 ? W0 : z == 1 ? W1 : W2);

    const int tid = threadIdx.x;
    const int w = tid >> 5, l = tid & 31, g = l >> 2, t = l & 3;
    const int wm = (w >> 2) * 64, wn = (w & 3) * 32;
    const int m0 = blockIdx.y * 128, n0 = blockIdx.x * 128;

    const uint32_t As_s = (uint32_t)__cvta_generic_to_shared(As);
    const uint32_t Ws_s = (uint32_t)__cvta_generic_to_shared(Ws);

    auto issue = [&](int ks, int buf) {
        #pragma unroll
        for (int j = 0; j < 4; j++) {             // A tile 128x32
            int id = j*256 + tid;
            int m = id >> 3, kq = (id & 7) * 4;
            cpa16(As_s + (uint32_t)(((buf*128 + m)*36 + kq) * 4),
                  Ar + (size_t)(m0 + m)*D_ + ks*32 + kq);
        }
        #pragma unroll
        for (int j = 0; j < 4; j++) {             // W tile 32x128
            int id = j*256 + tid;
            int k = id >> 5, nq = (id & 31) * 4;
            cpa16(Ws_s + (uint32_t)(((buf*32 + k)*132 + nq) * 4),
                  W + (size_t)(ks*32 + k)*D_ + n0 + nq);
        }
        asm volatile("cp.async.commit_group;\n");
    };

    float acc[4][4][4] = {};
    issue(0, 0);
    for (int s = 0; s < 24; s++) {
        const int buf = s & 1;
        asm volatile("cp.async.wait_group 0;\n");
        __syncthreads();                  // data in; all warps done prev mma
        if (s + 1 < 24) issue(s + 1, (s + 1) & 1);

        float* Ab = As + buf*128*36;
        float* Wb = Ws + buf*32*132;
        #pragma unroll
        for (int j = 0; j < 4; j++) {             // staging cvt A
            int id = j*256 + tid;
            float* p = Ab + (id >> 3)*36 + (id & 7)*4;
            float4 v = *(float4*)p;
            uint4 u = { f2tf(v.x), f2tf(v.y), f2tf(v.z), f2tf(v.w) };
            *(uint4*)p = u;
        }
        #pragma unroll
        for (int j = 0; j < 4; j++) {             // staging cvt W
            int id = j*256 + tid;
            float* p = Wb + (id >> 5)*132 + (id & 31)*4;
            float4 v = *(float4*)p;
            uint4 u = { f2tf(v.x), f2tf(v.y), f2tf(v.z), f2tf(v.w) };
            *(uint4*)p = u;
        }
        __syncthreads();

        const uint32_t* Au = (const uint32_t*)Ab;
        const uint32_t* Wu = (const uint32_t*)Wb;
        #pragma unroll
        for (int kt = 0; kt < 4; kt++) {
            uint32_t bf[4][2];
            #pragma unroll
            for (int nt = 0; nt < 4; nt++) {
                bf[nt][0] = Wu[(kt*8 + t    )*132 + wn + nt*8 + g];
                bf[nt][1] = Wu[(kt*8 + t + 4)*132 + wn + nt*8 + g];
            }
            #pragma unroll
            for (int mt = 0; mt < 4; mt++) {
                uint32_t af[4];
                int r = wm + mt*16 + g;
                af[0] = Au[ r     *36 + kt*8 + t    ];
                af[1] = Au[(r + 8)*36 + kt*8 + t    ];
                af[2] = Au[ r     *36 + kt*8 + t + 4];
                af[3] = Au[(r + 8)*36 + kt*8 + t + 4];
                #pragma unroll
                for (int nt = 0; nt < 4; nt++) mma8(acc[mt][nt], af, bf[nt]);
            }
        }
    }

    #pragma unroll
    for (int mt = 0; mt < 4; mt++)
    #pragma unroll
    for (int hh = 0; hh < 2; hh++) {
        int m = m0 + wm + mt*16 + hh*8 + g;
        #pragma unroll
        for (int nt = 0; nt < 4; nt++) {
            int n = n0 + wn + nt*8 + 2*t;
            float2 v = make_float2(acc[mt][nt][hh*2], acc[mt][nt][hh*2 + 1]);
            if (mode == 3) {
                *(float2*)(C + (size_t)m*D_ + n) = v;
            } else {
                float* out = (z == 0) ? g_Q : (z == 1) ? g_K : g_V;
                int h = n >> 6, dk = n & 63;
                int b = m >> 12, tt = m & 4095;
                *(float2*)(out + ((size_t)(b*H_ + h)*T_ + tt)*DK_ + dk) = v;
            }
        }
    }
}

// ===========================================================================
// Flash attention, tf32 mma. Block=(b,h,128 Q rows), 4 warps, Bc=64.
// K/V double-buffered via cp.async (raw fp32) + in-place RNA cvt staging.
// Q staged with 0.125*log2(e) folded in -> raw ex2 softmax.
// P: per-warp double-buffered 32x10 mini-tile (fp32 bits = tf32 RZ).
// ===========================================================================
#define LQ 68
#define PMW 320
#define ASM_BYTES (((128 + 2*64 + 2*64)*LQ)*4 + 4*2*PMW*4)   // 114688

__global__ __launch_bounds__(128) void attn2() {
    extern __shared__ float sa[];
    uint32_t* Qs = (uint32_t*)sa;          // [128][68] tf32(Q*0.1803)
    uint32_t* Ks = Qs + 128*LQ;            // [2][64][68]
    uint32_t* Vs = Ks + 2*64*LQ;           // [2][64][68]
    float*    Pm = (float*)(Vs + 2*64*LQ); // [4 warps][2 buf][32][10]

    const int qtile = blockIdx.x, h = blockIdx.y, b = blockIdx.z;
    const int tid = threadIdx.x;
    const int w = tid >> 5, l = tid & 31, g = l >> 2, t = l & 3;
    const int mw = w * 32;

    const float* Qg = g_Q + ((size_t)(b*H_ + h)*T_ + (size_t)qtile*128) * DK_;
    const float* Kg = g_K + (size_t)(b*H_ + h)*T_ * DK_;
    const float* Vg = g_V + (size_t)(b*H_ + h)*T_ * DK_;

    const uint32_t Ks_s = (uint32_t)__cvta_generic_to_shared(Ks);
    const uint32_t Vs_s = (uint32_t)__cvta_generic_to_shared(Vs);

    auto issueKV = [&](int it, int buf) {
        const float* Ksrc = Kg + (size_t)it*64*DK_;
        const float* Vsrc = Vg + (size_t)it*64*DK_;
        const uint32_t kb = Ks_s + (uint32_t)(buf*64*LQ*4);
        const uint32_t vb = Vs_s + (uint32_t)(buf*64*LQ*4);
        #pragma unroll
        for (int j = 0; j < 8; j++) {
            int idx = j*512 + tid*4;
            int r = idx >> 6, c = idx & 63;
            uint32_t off = (uint32_t)((r*LQ + c)*4);
            cpa16(kb + off, Ksrc + idx);
            cpa16(vb + off, Vsrc + idx);
        }
        asm volatile("cp.async.commit_group;\n");
    };

    issueKV(0, 0);                          // overlap with Q staging

    const float QSC = 0.180336881f;         // 0.125 * log2(e)
    #pragma unroll
    for (int it = 0; it < 16; it++) {
        int idx = it*512 + tid*4;
        int r = idx >> 6, c = idx & 63;
        float4 v = *(const float4*)(Qg + idx);
        uint4 u = { f2tf(v.x*QSC), f2tf(v.y*QSC), f2tf(v.z*QSC), f2tf(v.w*QSC) };
        *(uint4*)&Qs[r*LQ + c] = u;
    }

    float o[2][8][4] = {};
    float mi[2][2] = {{-1e30f,-1e30f},{-1e30f,-1e30f}};
    float li[2][2] = {};

    for (int it = 0; it < T_/64; it++) {
        const int buf = it & 1;
        asm volatile("cp.async.wait_group 0;\n");
        __syncthreads();                    // data in; all warps done prev PV
        if (it + 1 < T_/64) issueKV(it + 1, (it + 1) & 1);

        uint32_t* Kb = Ks + buf*64*LQ;
        uint32_t* Vb = Vs + buf*64*LQ;
        #pragma unroll
        for (int j = 0; j < 8; j++) {       // staging cvt K+V (RNA)
            int idx = j*512 + tid*4;
            uint32_t* kp = Kb + (idx >> 6)*LQ + (idx & 63);
            float4 kv = *(float4*)kp;
            uint4 uk = { f2tf(kv.x), f2tf(kv.y), f2tf(kv.z), f2tf(kv.w) };
            *(uint4*)kp = uk;
            uint32_t* vp = Vb + (idx >> 6)*LQ + (idx & 63);
            float4 vv = *(float4*)vp;
            uint4 uv = { f2tf(vv.x), f2tf(vv.y), f2tf(vv.z), f2tf(vv.w) };
            *(uint4*)vp = uv;
        }
        __syncthreads();

        // ---- S = Q @ K^T (log2 domain) ----
        float s[2][8][4] = {};
        #pragma unroll
        for (int kt = 0; kt < 8; kt++) {
            uint32_t bf[8][2];
            #pragma unroll
            for (int nt = 0; nt < 8; nt++) {
                bf[nt][0] = Kb[(nt*8 + g)*LQ + kt*8 + t    ];
                bf[nt][1] = Kb[(nt*8 + g)*LQ + kt*8 + t + 4];
            }
            #pragma unroll
            for (int mt = 0; mt < 2; mt++) {
                uint32_t af[4];
                int r = mw + mt*16 + g;
                af[0] = Qs[ r     *LQ + kt*8 + t    ];
                af[1] = Qs[(r + 8)*LQ + kt*8 + t    ];
                af[2] = Qs[ r     *LQ + kt*8 + t + 4];
                af[3] = Qs[(r + 8)*LQ + kt*8 + t + 4];
                #pragma unroll
                for (int nt = 0; nt < 8; nt++) mma8(s[mt][nt], af, bf[nt]);
            }
        }

        // ---- phase 1: row max, alpha, rescale O ----
        float al[2][2], mnr[2][2];
        #pragma unroll
        for (int mt = 0; mt < 2; mt++)
        #pragma unroll
        for (int hh = 0; hh < 2; hh++) {
            int ci = hh*2;
            float mx = -1e30f;
            #pragma unroll
            for (int nt = 0; nt < 8; nt++)
                mx = fmaxf(mx, fmaxf(s[mt][nt][ci], s[mt][nt][ci+1]));
            mx = fmaxf(mx, __shfl_xor_sync(0xffffffffu, mx, 1, 4));
            mx = fmaxf(mx, __shfl_xor_sync(0xffffffffu, mx, 2, 4));
            float mn = fmaxf(mi[mt][hh], mx);
            float a  = ex2f(mi[mt][hh] - mn);
            al[mt][hh] = a; mnr[mt][hh] = mn; mi[mt][hh] = mn;
            #pragma unroll
            for (int nt = 0; nt < 8; nt++) {
                o[mt][nt][ci]   *= a;
                o[mt][nt][ci+1] *= a;
            }
        }

        // ---- phase 2: per 8-col tile: exp -> mini-P -> PV mma ----
        float rs[2][2] = {};
        #pragma unroll
        for (int kt = 0; kt < 8; kt++) {
            float* Pw = Pm + (w*2 + (kt & 1))*PMW;
            #pragma unroll
            for (int mt = 0; mt < 2; mt++) {
                float p0 = ex2f(s[mt][kt][0] - mnr[mt][0]);
                float p1 = ex2f(s[mt][kt][1] - mnr[mt][0]);
                float p2 = ex2f(s[mt][kt][2] - mnr[mt][1]);
                float p3 = ex2f(s[mt][kt][3] - mnr[mt][1]);
                rs[mt][0] += p0 + p1;
                rs[mt][1] += p2 + p3;
                int rb = mt*16 + g;
                *(float2*)&Pw[ rb     *10 + 2*t] = make_float2(p0, p1);
                *(float2*)&Pw[(rb + 8)*10 + 2*t] = make_float2(p2, p3);
            }
            __syncwarp();
            uint32_t bv[8][2];
            #pragma unroll
            for (int nt = 0; nt < 8; nt++) {
                bv[nt][0] = Vb[(kt*8 + t    )*LQ + nt*8 + g];
                bv[nt][1] = Vb[(kt*8 + t + 4)*LQ + nt*8 + g];
            }
            #pragma unroll
            for (int mt = 0; mt < 2; mt++) {
                uint32_t pa[4];
                int rb = mt*16 + g;
                pa[0] = __float_as_uint(Pw[ rb     *10 + t    ]);
                pa[1] = __float_as_uint(Pw[(rb + 8)*10 + t    ]);
                pa[2] = __float_as_uint(Pw[ rb     *10 + t + 4]);
                pa[3] = __float_as_uint(Pw[(rb + 8)*10 + t + 4]);
                #pragma unroll
                for (int nt = 0; nt < 8; nt++) mma8(o[mt][nt], pa, bv[nt]);
            }
        }

        #pragma unroll
        for (int mt = 0; mt < 2; mt++)
        #pragma unroll
        for (int hh = 0; hh < 2; hh++) {
            float r = rs[mt][hh];
            r += __shfl_xor_sync(0xffffffffu, r, 1, 4);
            r += __shfl_xor_sync(0xffffffffu, r, 2, 4);
            li[mt][hh] = li[mt][hh]*al[mt][hh] + r;
        }
    }

    #pragma unroll
    for (int mt = 0; mt < 2; mt++)
    #pragma unroll
    for (int hh = 0; hh < 2; hh++) {
        float inv = 1.f / li[mt][hh];
        int r = qtile*128 + mw + mt*16 + hh*8 + g;
        float* dst = g_O + ((size_t)b*T_ + r)*D_ + h*DK_;
        #pragma unroll
        for (int nt = 0; nt < 8; nt++) {
            float2 v = make_float2(o[mt][nt][hh*2]*inv, o[mt][nt][hh*2+1]*inv);
            *(float2*)(dst + nt*8 + 2*t) = v;
        }
    }
}

// ===========================================================================
extern "C" void kernel_launch(void* const* d_in, const int* in_sizes, int n_in,
                              void* d_out, int out_size) {
    const float* x  = (const float*)d_in[0];
    const float* WQ = (const float*)d_in[1];
    const float* WK = (const float*)d_in[2];
    const float* WV = (const float*)d_in[3];
    const float* Wp = (const float*)d_in[4];
    float* out = (float*)d_out;

    cudaFuncSetAttribute(gemm2, cudaFuncAttributeMaxDynamicSharedMemorySize,
                         GSM_BYTES);
    cudaFuncSetAttribute(attn2, cudaFuncAttributeMaxDynamicSharedMemorySize,
                         ASM_BYTES);

    dim3 gq(D_/128, M_/128, 3);           // fused QKV
    gemm2<<<gq, 256, GSM_BYTES>>>(x, WQ, WK, WV, nullptr, -1);

    dim3 ga(T_/128, H_, B_);              // (32, 12, 2)
    attn2<<<ga, 128, ASM_BYTES>>>();

    dim3 gp(D_/128, M_/128, 1);
    gemm2<<<gp, 256, GSM_BYTES>>>(nullptr, Wp, Wp, Wp, out, 3);
}

// round 9
// speedup vs baseline: 1.6952x; 1.6952x over previous
#include <cuda_runtime.h>
#include <cuda_fp16.h>
#include <cstdint>

#define B_  2
#define T_  4096
#define D_  768
#define H_  12
#define DK_ 64
#define M_  (B_*T_)   // 8192

// Scratch (allocation-free)
__device__ float g_Q[B_*H_*T_*DK_];
__device__ float g_K[B_*H_*T_*DK_];
__device__ float g_V[B_*H_*T_*DK_];
__device__ float g_O[M_*D_];

__device__ __forceinline__ uint32_t f2tf(float f) {
    uint32_t r; asm("cvt.rna.tf32.f32 %0, %1;" : "=r"(r) : "f"(f)); return r;
}
__device__ __forceinline__ float ex2f(float x) {
    float y; asm("ex2.approx.f32 %0, %1;" : "=f"(y) : "f"(x)); return y;
}
__device__ __forceinline__ uint32_t packh2(float lo, float hi) {
    uint32_t r;  // d.hi = first src, d.lo = second src
    asm("cvt.rn.f16x2.f32 %0, %1, %2;" : "=r"(r) : "f"(hi), "f"(lo));
    return r;
}
__device__ __forceinline__ void mma8(float* c, const uint32_t* a, const uint32_t* b) {
    asm volatile("mma.sync.aligned.m16n8k8.row.col.f32.tf32.tf32.f32 "
        "{%0,%1,%2,%3}, {%4,%5,%6,%7}, {%8,%9}, {%0,%1,%2,%3};"
        : "+f"(c[0]), "+f"(c[1]), "+f"(c[2]), "+f"(c[3])
        : "r"(a[0]), "r"(a[1]), "r"(a[2]), "r"(a[3]), "r"(b[0]), "r"(b[1]));
}
__device__ __forceinline__ void mma16(float* c, const uint32_t* a, const uint32_t* b) {
    asm volatile("mma.sync.aligned.m16n8k16.row.col.f32.f16.f16.f32 "
        "{%0,%1,%2,%3}, {%4,%5,%6,%7}, {%8,%9}, {%0,%1,%2,%3};"
        : "+f"(c[0]), "+f"(c[1]), "+f"(c[2]), "+f"(c[3])
        : "r"(a[0]), "r"(a[1]), "r"(a[2]), "r"(a[3]), "r"(b[0]), "r"(b[1]));
}
__device__ __forceinline__ void ldsm4(uint32_t* r, uint32_t addr) {
    asm volatile("ldmatrix.sync.aligned.m8n8.x4.shared.b16 {%0,%1,%2,%3}, [%4];"
        : "=r"(r[0]), "=r"(r[1]), "=r"(r[2]), "=r"(r[3]) : "r"(addr));
}
__device__ __forceinline__ void ldsm4t(uint32_t* r, uint32_t addr) {
    asm volatile("ldmatrix.sync.aligned.m8n8.x4.trans.shared.b16 {%0,%1,%2,%3}, [%4];"
        : "=r"(r[0]), "=r"(r[1]), "=r"(r[2]), "=r"(r[3]) : "r"(addr));
}
__device__ __forceinline__ void cpa16(uint32_t dst, const float* src) {
    asm volatile("cp.async.cg.shared.global [%0], [%1], 16;\n" :: "r"(dst), "l"(src));
}

// ===========================================================================
// GEMM (exact R6 version, measured 207us QKV): tf32, block 128x128, k-step 32,
// 256 thr, cp.async double-buffered, cvt at fragment load.
// ===========================================================================
#define GSM_BYTES ((2*128*36 + 2*32*132) * 4)   // 70656

__global__ __launch_bounds__(256, 2) void gemm2(
        const float* __restrict__ A,
        const float* __restrict__ W0, const float* __restrict__ W1,
        const float* __restrict__ W2,
        float* __restrict__ C, int mode) {
    extern __shared__ float sg[];
    float* As = sg;                  // [2][128][36]
    float* Ws = sg + 2*128*36;       // [2][32][132]
    const float* Ar = A ? A : g_O;
    const int z = blockIdx.z;
    const float* W = (mode == 3) ? W0 : (z == 0 ? W0 : z == 1 ? W1 : W2);

    const int tid = threadIdx.x;
    const int w = tid >> 5, l = tid & 31, g = l >> 2, t = l & 3;
    const int wm = (w >> 2) * 64, wn = (w & 3) * 32;
    const int m0 = blockIdx.y * 128, n0 = blockIdx.x * 128;

    const uint32_t As_s = (uint32_t)__cvta_generic_to_shared(As);
    const uint32_t Ws_s = (uint32_t)__cvta_generic_to_shared(Ws);

    auto issue = [&](int ks, int buf) {
        #pragma unroll
        for (int j = 0; j < 4; j++) {
            int id = j*256 + tid;
            int m = id >> 3, kq = (id & 7) * 4;
            cpa16(As_s + (uint32_t)(((buf*128 + m)*36 + kq) * 4),
                  Ar + (size_t)(m0 + m)*D_ + ks*32 + kq);
        }
        #pragma unroll
        for (int j = 0; j < 4; j++) {
            int id = j*256 + tid;
            int k = id >> 5, nq = (id & 31) * 4;
            cpa16(Ws_s + (uint32_t)(((buf*32 + k)*132 + nq) * 4),
                  W + (size_t)(ks*32 + k)*D_ + n0 + nq);
        }
        asm volatile("cp.async.commit_group;\n");
    };

    float acc[4][4][4] = {};
    issue(0, 0);
    for (int s = 0; s < 24; s++) {
        const int buf = s & 1;
        if (s + 1 < 24) {
            issue(s + 1, (s + 1) & 1);
            asm volatile("cp.async.wait_group 1;\n");
        } else {
            asm volatile("cp.async.wait_group 0;\n");
        }
        __syncthreads();
        const float* Ab = As + buf*128*36;
        const float* Wb = Ws + buf*32*132;
        #pragma unroll
        for (int kt = 0; kt < 4; kt++) {
            uint32_t bf[4][2];
            #pragma unroll
            for (int nt = 0; nt < 4; nt++) {
                bf[nt][0] = f2tf(Wb[(kt*8 + t    )*132 + wn + nt*8 + g]);
                bf[nt][1] = f2tf(Wb[(kt*8 + t + 4)*132 + wn + nt*8 + g]);
            }
            #pragma unroll
            for (int mt = 0; mt < 4; mt++) {
                uint32_t af[4];
                int r = wm + mt*16 + g;
                af[0] = f2tf(Ab[ r     *36 + kt*8 + t    ]);
                af[1] = f2tf(Ab[(r + 8)*36 + kt*8 + t    ]);
                af[2] = f2tf(Ab[ r     *36 + kt*8 + t + 4]);
                af[3] = f2tf(Ab[(r + 8)*36 + kt*8 + t + 4]);
                #pragma unroll
                for (int nt = 0; nt < 4; nt++) mma8(acc[mt][nt], af, bf[nt]);
            }
        }
        __syncthreads();
    }

    #pragma unroll
    for (int mt = 0; mt < 4; mt++)
    #pragma unroll
    for (int hh = 0; hh < 2; hh++) {
        int m = m0 + wm + mt*16 + hh*8 + g;
        #pragma unroll
        for (int nt = 0; nt < 4; nt++) {
            int n = n0 + wn + nt*8 + 2*t;
            float2 v = make_float2(acc[mt][nt][hh*2], acc[mt][nt][hh*2 + 1]);
            if (mode == 3) {
                *(float2*)(C + (size_t)m*D_ + n) = v;
            } else {
                float* out = (z == 0) ? g_Q : (z == 1) ? g_K : g_V;
                int h = n >> 6, dk = n & 63;
                int b = m >> 12, tt = m & 4095;
                *(float2*)(out + ((size_t)(b*H_ + h)*T_ + tt)*DK_ + dk) = v;
            }
        }
    }
}

// ===========================================================================
// Flash attention, fp16 m16n8k16, register-resident P.
// Block = (b,h,128 Q rows), 256 thr, 8 warps (warp = 16 rows), Bc = 64.
// Q*0.125*log2(e) in fp16 smem; all fragments via ldmatrix.x4 (V transposed
// at load). S C-frag -> exp(fp32) -> pack f16x2 == PV A-frag: P has no smem.
// ===========================================================================
#define LH 72   // halves per smem row
// smem: Q[128][72] + K[64][72] + V[64][72] halves = 36864 B (static)

__global__ __launch_bounds__(256, 2) void attn3() {
    __shared__ __half sh[(128 + 64 + 64) * LH];
    __half* Qs = sh;
    __half* Ks = Qs + 128*LH;
    __half* Vs = Ks + 64*LH;

    const int qtile = blockIdx.x, h = blockIdx.y, b = blockIdx.z;
    const int tid = threadIdx.x;
    const int w = tid >> 5, l = tid & 31, g = l >> 2, t = l & 3;
    const int mw = w * 16;

    const float* Qg = g_Q + ((size_t)(b*H_ + h)*T_ + (size_t)qtile*128) * DK_;
    const float* Kg = g_K + (size_t)(b*H_ + h)*T_ * DK_;
    const float* Vg = g_V + (size_t)(b*H_ + h)*T_ * DK_;

    const uint32_t Qb = (uint32_t)__cvta_generic_to_shared(Qs);
    const uint32_t Kb = (uint32_t)__cvta_generic_to_shared(Ks);
    const uint32_t Vb = (uint32_t)__cvta_generic_to_shared(Vs);

    // ldmatrix lane address components
    const int qrow = mw + ((l >> 3) & 1)*8 + (l & 7);   // + kt*16 col, +(l>>4)*8
    const int qcol = ((l >> 4) & 1) * 8;
    const int krow = ((l >> 4) & 1)*8 + (l & 7);        // + nt2*16
    const int kcol = ((l >> 3) & 1) * 8;                // + kt*16
    const int vrow = ((l >> 3) & 1)*8 + (l & 7);        // + kt*16
    const int vcol = ((l >> 4) & 1) * 8;                // + nt2*16

    // ---- stage Q (fold 0.125*log2e) ----
    const float QSC = 0.180336881f;
    #pragma unroll
    for (int it = 0; it < 8; it++) {
        int idx = it*1024 + tid*4;
        int r = idx >> 6, c = idx & 63;
        float4 v = *(const float4*)(Qg + idx);
        uint2 u = { packh2(v.x*QSC, v.y*QSC), packh2(v.z*QSC, v.w*QSC) };
        *(uint2*)&Qs[r*LH + c] = u;
    }

    float o[8][4] = {};
    float mi[2] = {-1e30f, -1e30f};
    float li[2] = {0.f, 0.f};

    for (int kv = 0; kv < T_/64; kv++) {
        __syncthreads();                       // prev iter done reading K/V
        #pragma unroll
        for (int j = 0; j < 4; j++) {          // K,V tiles 64x64
            int idx = j*1024 + tid*4;
            int r = idx >> 6, c = idx & 63;
            float4 kf = *(const float4*)(Kg + (size_t)kv*64*DK_ + idx);
            uint2 uk = { packh2(kf.x, kf.y), packh2(kf.z, kf.w) };
            *(uint2*)&Ks[r*LH + c] = uk;
            float4 vf = *(const float4*)(Vg + (size_t)kv*64*DK_ + idx);
            uint2 uv = { packh2(vf.x, vf.y), packh2(vf.z, vf.w) };
            *(uint2*)&Vs[r*LH + c] = uv;
        }
        __syncthreads();

        // ---- S = Q @ K^T (log2 domain) ----
        float s[8][4] = {};
        #pragma unroll
        for (int kt = 0; kt < 4; kt++) {
            uint32_t a[4];
            ldsm4(a, Qb + (uint32_t)((qrow*LH + kt*16 + qcol) * 2));
            #pragma unroll
            for (int nt2 = 0; nt2 < 4; nt2++) {
                uint32_t kr[4];
                ldsm4(kr, Kb + (uint32_t)(((nt2*16 + krow)*LH + kt*16 + kcol) * 2));
                mma16(s[2*nt2],     a, kr);
                mma16(s[2*nt2 + 1], a, kr + 2);
            }
        }

        // ---- online softmax (rows g / g+8; 4 lanes share a row) ----
        float mx0 = -1e30f, mx1 = -1e30f;
        #pragma unroll
        for (int nt = 0; nt < 8; nt++) {
            mx0 = fmaxf(mx0, fmaxf(s[nt][0], s[nt][1]));
            mx1 = fmaxf(mx1, fmaxf(s[nt][2], s[nt][3]));
        }
        mx0 = fmaxf(mx0, __shfl_xor_sync(0xffffffffu, mx0, 1, 4));
        mx0 = fmaxf(mx0, __shfl_xor_sync(0xffffffffu, mx0, 2, 4));
        mx1 = fmaxf(mx1, __shfl_xor_sync(0xffffffffu, mx1, 1, 4));
        mx1 = fmaxf(mx1, __shfl_xor_sync(0xffffffffu, mx1, 2, 4));
        float mn0 = fmaxf(mi[0], mx0), mn1 = fmaxf(mi[1], mx1);
        float al0 = ex2f(mi[0] - mn0), al1 = ex2f(mi[1] - mn1);
        mi[0] = mn0; mi[1] = mn1;

        uint32_t ph[8][2];
        float rs0 = 0.f, rs1 = 0.f;
        #pragma unroll
        for (int nt = 0; nt < 8; nt++) {
            float p0 = ex2f(s[nt][0] - mn0);
            float p1 = ex2f(s[nt][1] - mn0);
            float p2 = ex2f(s[nt][2] - mn1);
            float p3 = ex2f(s[nt][3] - mn1);
            rs0 += p0 + p1;  rs1 += p2 + p3;
            ph[nt][0] = packh2(p0, p1);        // P(row g,   cols 2t,2t+1)
            ph[nt][1] = packh2(p2, p3);        // P(row g+8, cols 2t,2t+1)
            o[nt][0] *= al0; o[nt][1] *= al0;
            o[nt][2] *= al1; o[nt][3] *= al1;
        }
        rs0 += __shfl_xor_sync(0xffffffffu, rs0, 1, 4);
        rs0 += __shfl_xor_sync(0xffffffffu, rs0, 2, 4);
        rs1 += __shfl_xor_sync(0xffffffffu, rs1, 1, 4);
        rs1 += __shfl_xor_sync(0xffffffffu, rs1, 2, 4);
        li[0] = li[0]*al0 + rs0;
        li[1] = li[1]*al1 + rs1;

        // ---- O += P @ V  (P straight from registers) ----
        #pragma unroll
        for (int kt = 0; kt < 4; kt++) {
            uint32_t pa[4] = { ph[2*kt][0], ph[2*kt][1],
                               ph[2*kt+1][0], ph[2*kt+1][1] };
            #pragma unroll
            for (int nt2 = 0; nt2 < 4; nt2++) {
                uint32_t bv[4];
                ldsm4t(bv, Vb + (uint32_t)(((kt*16 + vrow)*LH + nt2*16 + vcol) * 2));
                mma16(o[2*nt2],     pa, bv);
                mma16(o[2*nt2 + 1], pa, bv + 2);
            }
        }
    }

    // ---- normalize + write [B,T,D] ----
    float inv0 = 1.f / li[0], inv1 = 1.f / li[1];
    int r0 = qtile*128 + mw + g;
    float* dst0 = g_O + ((size_t)b*T_ + r0    )*D_ + h*DK_;
    float* dst1 = g_O + ((size_t)b*T_ + r0 + 8)*D_ + h*DK_;
    #pragma unroll
    for (int nt = 0; nt < 8; nt++) {
        *(float2*)(dst0 + nt*8 + 2*t) = make_float2(o[nt][0]*inv0, o[nt][1]*inv0);
        *(float2*)(dst1 + nt*8 + 2*t) = make_float2(o[nt][2]*inv1, o[nt][3]*inv1);
    }
}

// ===========================================================================
extern "C" void kernel_launch(void* const* d_in, const int* in_sizes, int n_in,
                              void* d_out, int out_size) {
    const float* x  = (const float*)d_in[0];
    const float* WQ = (const float*)d_in[1];
    const float* WK = (const float*)d_in[2];
    const float* WV = (const float*)d_in[3];
    const float* Wp = (const float*)d_in[4];
    float* out = (float*)d_out;

    cudaFuncSetAttribute(gemm2, cudaFuncAttributeMaxDynamicSharedMemorySize,
                         GSM_BYTES);

    dim3 gq(D_/128, M_/128, 3);           // fused QKV
    gemm2<<<gq, 256, GSM_BYTES>>>(x, WQ, WK, WV, nullptr, -1);

    dim3 ga(T_/128, H_, B_);              // (32, 12, 2)
    attn3<<<ga, 256>>>();

    dim3 gp(D_/128, M_/128, 1);
    gemm2<<<gp, 256, GSM_BYTES>>>(nullptr, Wp, Wp, Wp, out, 3);
}

// round 13
// speedup vs baseline: 2.3748x; 1.4008x over previous
#include <cuda_runtime.h>
#include <cuda_fp16.h>
#include <cstdint>

#define B_  2
#define T_  4096
#define D_  768
#define H_  12
#define DK_ 64
#define M_  (B_*T_)   // 8192

// Scratch (allocation-free): everything fp16 except final output
__device__ __half g_xh[M_*D_];
__device__ __half g_Wh[4][D_*D_];          // WQ, WK, WV, Wproj
__device__ __half g_Qh[B_*H_*T_*DK_];      // pre-scaled by 0.125*log2e
__device__ __half g_Kh[B_*H_*T_*DK_];
__device__ __half g_Vh[B_*H_*T_*DK_];
__device__ __half g_Oh[M_*D_];

__device__ __forceinline__ float ex2f(float x) {
    float y; asm("ex2.approx.f32 %0, %1;" : "=f"(y) : "f"(x)); return y;
}
__device__ __forceinline__ uint32_t packh2(float lo, float hi) {
    uint32_t r;
    asm("cvt.rn.f16x2.f32 %0, %1, %2;" : "=r"(r) : "f"(hi), "f"(lo));
    return r;
}
__device__ __forceinline__ void mma16(float* c, const uint32_t* a, const uint32_t* b) {
    asm volatile("mma.sync.aligned.m16n8k16.row.col.f32.f16.f16.f32 "
        "{%0,%1,%2,%3}, {%4,%5,%6,%7}, {%8,%9}, {%0,%1,%2,%3};"
        : "+f"(c[0]), "+f"(c[1]), "+f"(c[2]), "+f"(c[3])
        : "r"(a[0]), "r"(a[1]), "r"(a[2]), "r"(a[3]), "r"(b[0]), "r"(b[1]));
}
__device__ __forceinline__ void ldsm4(uint32_t* r, uint32_t addr) {
    asm volatile("ldmatrix.sync.aligned.m8n8.x4.shared.b16 {%0,%1,%2,%3}, [%4];"
        : "=r"(r[0]), "=r"(r[1]), "=r"(r[2]), "=r"(r[3]) : "r"(addr));
}
__device__ __forceinline__ void ldsm4t(uint32_t* r, uint32_t addr) {
    asm volatile("ldmatrix.sync.aligned.m8n8.x4.trans.shared.b16 {%0,%1,%2,%3}, [%4];"
        : "=r"(r[0]), "=r"(r[1]), "=r"(r[2]), "=r"(r[3]) : "r"(addr));
}
__device__ __forceinline__ void cpa16(uint32_t dst, const void* src) {
    asm volatile("cp.async.cg.shared.global [%0], [%1], 16;\n" :: "r"(dst), "l"(src));
}

#define QSC 0.180336881f   // 0.125 * log2(e)

// ===========================================================================
// One-shot fp32 -> fp16 conversion of x and the 4 weight matrices.
// ===========================================================================
__global__ void cvt_kernel(const float* __restrict__ x,
                           const float* __restrict__ wq, const float* __restrict__ wk,
                           const float* __restrict__ wv, const float* __restrict__ wp) {
    const int X4 = M_*D_/4;        // 1572864
    const int W4 = D_*D_/4;        // 147456
    for (int i = blockIdx.x*blockDim.x + threadIdx.x; i < X4 + 4*W4;
         i += gridDim.x*blockDim.x) {
        const float* src; __half* dst; int off;
        if (i < X4) { src = x; dst = g_xh; off = i; }
        else {
            int j = i - X4, ws = j / W4; off = j - ws*W4;
            src = (ws == 0) ? wq : (ws == 1) ? wk : (ws == 2) ? wv : wp;
            dst = g_Wh[ws];
        }
        float4 v = ((const float4*)src)[off];
        uint2 u = { packh2(v.x, v.y), packh2(v.z, v.w) };
        *(uint2*)(dst + off*4) = u;
    }
}

// ===========================================================================
// fp16 GEMM: block 128x128, k-step 64, 256 thr, 8 warps (warp 64x32),
// cp.async double-buffered fp16 smem, ldmatrix fragments, m16n8k16 HMMA.
// mode -1: A=g_xh, W=g_Wh[z] -> g_Qh/g_Kh/g_Vh (split-head; Q scaled by QSC).
// mode  3: A=g_Oh, W=g_Wh[3] -> fp32 row-major C.
// ===========================================================================
#define LA 72    // A row halves (64 + 8 pad)
#define LB 136   // W row halves (128 + 8 pad)
#define GH_BYTES ((2*128*LA + 2*64*LB) * 2)   // 36864 + 34816 = 71680

__global__ __launch_bounds__(256, 2) void gemm_h(float* __restrict__ Cf, int mode) {
    extern __shared__ __half shg[];
    __half* As = shg;                   // [2][128][72]
    __half* Ws = shg + 2*128*LA;        // [2][64][136]
    const int z = blockIdx.z;
    const __half* A = (mode == 3) ? g_Oh : g_xh;
    const __half* W = (mode == 3) ? g_Wh[3] : g_Wh[z];

    const int tid = threadIdx.x;
    const int w = tid >> 5, l = tid & 31, g = l >> 2, t = l & 3;
    const int wm = (w >> 2) * 64, wn = (w & 3) * 32;
    const int m0 = blockIdx.y * 128, n0 = blockIdx.x * 128;

    const uint32_t As_s = (uint32_t)__cvta_generic_to_shared(As);
    const uint32_t Ws_s = (uint32_t)__cvta_generic_to_shared(Ws);

    auto issue = [&](int ks, int buf) {
        #pragma unroll
        for (int j = 0; j < 4; j++) {              // A tile 128x64 halves
            int id = j*256 + tid;
            int m = id >> 3, c = (id & 7) * 8;
            cpa16(As_s + (uint32_t)(((buf*128 + m)*LA + c) * 2),
                  A + (size_t)(m0 + m)*D_ + ks*64 + c);
        }
        #pragma unroll
        for (int j = 0; j < 4; j++) {              // W tile 64x128 halves
            int id = j*256 + tid;
            int k = id >> 4, c = (id & 15) * 8;
            cpa16(Ws_s + (uint32_t)(((buf*64 + k)*LB + c) * 2),
                  W + (size_t)(ks*64 + k)*D_ + n0 + c);
        }
        asm volatile("cp.async.commit_group;\n");
    };

    // ldmatrix lane addressing
    const int arow = ((l >> 3) & 1)*8 + (l & 7);   // + wm + mt*16
    const int acol = ((l >> 4) & 1)*8;             // + kt*16
    const int brow = ((l >> 3) & 1)*8 + (l & 7);   // + kt*16 (k dim)
    const int bcol = ((l >> 4) & 1)*8;             // + wn + nt2*16

    float acc[4][4][4] = {};
    issue(0, 0);
    for (int s = 0; s < 12; s++) {
        const int buf = s & 1;
        if (s + 1 < 12) {
            issue(s + 1, (s + 1) & 1);
            asm volatile("cp.async.wait_group 1;\n");
        } else {
            asm volatile("cp.async.wait_group 0;\n");
        }
        __syncthreads();

        const uint32_t Ab = As_s + (uint32_t)(buf*128*LA*2);
        const uint32_t Wb = Ws_s + (uint32_t)(buf*64*LB*2);
        #pragma unroll
        for (int kt = 0; kt < 4; kt++) {
            uint32_t bv[2][4];
            #pragma unroll
            for (int nt2 = 0; nt2 < 2; nt2++)
                ldsm4t(bv[nt2], Wb + (uint32_t)(((kt*16 + brow)*LB
                                   + wn + nt2*16 + bcol) * 2));
            #pragma unroll
            for (int mt = 0; mt < 4; mt++) {
                uint32_t a[4];
                ldsm4(a, Ab + (uint32_t)(((wm + mt*16 + arow)*LA
                                 + kt*16 + acol) * 2));
                #pragma unroll
                for (int nt2 = 0; nt2 < 2; nt2++) {
                    mma16(acc[mt][nt2*2],     a, bv[nt2]);
                    mma16(acc[mt][nt2*2 + 1], a, bv[nt2] + 2);
                }
            }
        }
        __syncthreads();
    }

    const float scl = (mode != 3 && z == 0) ? QSC : 1.f;
    #pragma unroll
    for (int mt = 0; mt < 4; mt++)
    #pragma unroll
    for (int hh = 0; hh < 2; hh++) {
        int m = m0 + wm + mt*16 + hh*8 + g;
        #pragma unroll
        for (int nt = 0; nt < 4; nt++) {
            int n = n0 + wn + nt*8 + 2*t;
            float c0 = acc[mt][nt][hh*2] * scl, c1 = acc[mt][nt][hh*2 + 1] * scl;
            if (mode == 3) {
                *(float2*)(Cf + (size_t)m*D_ + n) = make_float2(c0, c1);
            } else {
                __half* out = (z == 0) ? g_Qh : (z == 1) ? g_Kh : g_Vh;
                int h = n >> 6, dk = n & 63;
                int b = m >> 12, tt = m & 4095;
                *(uint32_t*)(out + ((size_t)(b*H_ + h)*T_ + tt)*DK_ + dk)
                    = packh2(c0, c1);
            }
        }
    }
}

// ===========================================================================
// Flash attention, fp16 m16n8k16, register-resident P, cp.async
// double-buffered K/V (data already fp16 -> no staging conversion).
// Block = (b,h,128 Q rows), 256 thr, 8 warps (warp = 16 rows), Bc = 64.
// ===========================================================================
#define LH 72
#define ASM_BYTES ((128 + 2*64 + 2*64) * LH * 2)   // 55296

__global__ __launch_bounds__(256, 2) void attn4() {
    extern __shared__ __half sh[];
    __half* Qs = sh;                   // [128][72]
    __half* Ks = Qs + 128*LH;          // [2][64][72]
    __half* Vs = Ks + 2*64*LH;         // [2][64][72]

    const int qtile = blockIdx.x, h = blockIdx.y, b = blockIdx.z;
    const int tid = threadIdx.x;
    const int w = tid >> 5, l = tid & 31, g = l >> 2, t = l & 3;
    const int mw = w * 16;

    const __half* Qg = g_Qh + ((size_t)(b*H_ + h)*T_ + (size_t)qtile*128) * DK_;
    const __half* Kg = g_Kh + (size_t)(b*H_ + h)*T_ * DK_;
    const __half* Vg = g_Vh + (size_t)(b*H_ + h)*T_ * DK_;

    const uint32_t Qb = (uint32_t)__cvta_generic_to_shared(Qs);
    const uint32_t Kb = (uint32_t)__cvta_generic_to_shared(Ks);
    const uint32_t Vb = (uint32_t)__cvta_generic_to_shared(Vs);

    const int qrow = mw + ((l >> 3) & 1)*8 + (l & 7);
    const int qcol = ((l >> 4) & 1) * 8;
    const int krow = ((l >> 4) & 1)*8 + (l & 7);
    const int kcol = ((l >> 3) & 1) * 8;
    const int vrow = ((l >> 3) & 1)*8 + (l & 7);
    const int vcol = ((l >> 4) & 1) * 8;

    auto issueKV = [&](int it, int buf) {
        const __half* Ksrc = Kg + (size_t)it*64*DK_;
        const __half* Vsrc = Vg + (size_t)it*64*DK_;
        const uint32_t kb = Kb + (uint32_t)(buf*64*LH*2);
        const uint32_t vb = Vb + (uint32_t)(buf*64*LH*2);
        #pragma unroll
        for (int j = 0; j < 2; j++) {
            int id = j*256 + tid;                  // 0..511
            int r = id >> 3, c = (id & 7) * 8;
            cpa16(kb + (uint32_t)((r*LH + c)*2), Ksrc + r*DK_ + c);
            cpa16(vb + (uint32_t)((r*LH + c)*2), Vsrc + r*DK_ + c);
        }
        asm volatile("cp.async.commit_group;\n");
    };

    // Q tile (1024 chunks) + first KV in one group
    #pragma unroll
    for (int j = 0; j < 4; j++) {
        int id = j*256 + tid;
        int r = id >> 3, c = (id & 7) * 8;
        cpa16(Qb + (uint32_t)((r*LH + c)*2), Qg + r*DK_ + c);
    }
    issueKV(0, 0);

    float o[8][4] = {};
    float mi[2] = {-1e30f, -1e30f};
    float li[2] = {0.f, 0.f};

    for (int kv = 0; kv < T_/64; kv++) {
        const int buf = kv & 1;
        asm volatile("cp.async.wait_group 0;\n");
        __syncthreads();                           // data in; prev iter done
        if (kv + 1 < T_/64) issueKV(kv + 1, (kv + 1) & 1);

        const uint32_t Kbb = Kb + (uint32_t)(buf*64*LH*2);
        const uint32_t Vbb = Vb + (uint32_t)(buf*64*LH*2);

        // ---- S = Q @ K^T (log2 domain; QSC pre-folded into g_Qh) ----
        float s[8][4] = {};
        #pragma unroll
        for (int kt = 0; kt < 4; kt++) {
            uint32_t a[4];
            ldsm4(a, Qb + (uint32_t)((qrow*LH + kt*16 + qcol) * 2));
            #pragma unroll
            for (int nt2 = 0; nt2 < 4; nt2++) {
                uint32_t kr[4];
                ldsm4(kr, Kbb + (uint32_t)(((nt2*16 + krow)*LH + kt*16 + kcol) * 2));
                mma16(s[2*nt2],     a, kr);
                mma16(s[2*nt2 + 1], a, kr + 2);
            }
        }

        // ---- online softmax ----
        float mx0 = -1e30f, mx1 = -1e30f;
        #pragma unroll
        for (int nt = 0; nt < 8; nt++) {
            mx0 = fmaxf(mx0, fmaxf(s[nt][0], s[nt][1]));
            mx1 = fmaxf(mx1, fmaxf(s[nt][2], s[nt][3]));
        }
        mx0 = fmaxf(mx0, __shfl_xor_sync(0xffffffffu, mx0, 1, 4));
        mx0 = fmaxf(mx0, __shfl_xor_sync(0xffffffffu, mx0, 2, 4));
        mx1 = fmaxf(mx1, __shfl_xor_sync(0xffffffffu, mx1, 1, 4));
        mx1 = fmaxf(mx1, __shfl_xor_sync(0xffffffffu, mx1, 2, 4));
        float mn0 = fmaxf(mi[0], mx0), mn1 = fmaxf(mi[1], mx1);
        float al0 = ex2f(mi[0] - mn0), al1 = ex2f(mi[1] - mn1);
        mi[0] = mn0; mi[1] = mn1;

        uint32_t ph[8][2];
        float rs0 = 0.f, rs1 = 0.f;
        #pragma unroll
        for (int nt = 0; nt < 8; nt++) {
            float p0 = ex2f(s[nt][0] - mn0);
            float p1 = ex2f(s[nt][1] - mn0);
            float p2 = ex2f(s[nt][2] - mn1);
            float p3 = ex2f(s[nt][3] - mn1);
            rs0 += p0 + p1;  rs1 += p2 + p3;
            ph[nt][0] = packh2(p0, p1);
            ph[nt][1] = packh2(p2, p3);
            o[nt][0] *= al0; o[nt][1] *= al0;
            o[nt][2] *= al1; o[nt][3] *= al1;
        }
        rs0 += __shfl_xor_sync(0xffffffffu, rs0, 1, 4);
        rs0 += __shfl_xor_sync(0xffffffffu, rs0, 2, 4);
        rs1 += __shfl_xor_sync(0xffffffffu, rs1, 1, 4);
        rs1 += __shfl_xor_sync(0xffffffffu, rs1, 2, 4);
        li[0] = li[0]*al0 + rs0;
        li[1] = li[1]*al1 + rs1;

        // ---- O += P @ V (P straight from registers) ----
        #pragma unroll
        for (int kt = 0; kt < 4; kt++) {
            uint32_t pa[4] = { ph[2*kt][0], ph[2*kt][1],
                               ph[2*kt+1][0], ph[2*kt+1][1] };
            #pragma unroll
            for (int nt2 = 0; nt2 < 4; nt2++) {
                uint32_t bv[4];
                ldsm4t(bv, Vbb + (uint32_t)(((kt*16 + vrow)*LH + nt2*16 + vcol) * 2));
                mma16(o[2*nt2],     pa, bv);
                mma16(o[2*nt2 + 1], pa, bv + 2);
            }
        }
    }

    // ---- normalize + write g_Oh (fp16) ----
    float inv0 = 1.f / li[0], inv1 = 1.f / li[1];
    int r0 = qtile*128 + mw + g;
    __half* dst0 = g_Oh + ((size_t)b*T_ + r0    )*D_ + h*DK_;
    __half* dst1 = g_Oh + ((size_t)b*T_ + r0 + 8)*D_ + h*DK_;
    #pragma unroll
    for (int nt = 0; nt < 8; nt++) {
        *(uint32_t*)(dst0 + nt*8 + 2*t) = packh2(o[nt][0]*inv0, o[nt][1]*inv0);
        *(uint32_t*)(dst1 + nt*8 + 2*t) = packh2(o[nt][2]*inv1, o[nt][3]*inv1);
    }
}

// ===========================================================================
extern "C" void kernel_launch(void* const* d_in, const int* in_sizes, int n_in,
                              void* d_out, int out_size) {
    const float* x  = (const float*)d_in[0];
    const float* WQ = (const float*)d_in[1];
    const float* WK = (const float*)d_in[2];
    const float* WV = (const float*)d_in[3];
    const float* Wp = (const float*)d_in[4];
    float* out = (float*)d_out;

    cudaFuncSetAttribute(gemm_h, cudaFuncAttributeMaxDynamicSharedMemorySize,
                         GH_BYTES);
    cudaFuncSetAttribute(attn4, cudaFuncAttributeMaxDynamicSharedMemorySize,
                         ASM_BYTES);

    cvt_kernel<<<512, 256>>>(x, WQ, WK, WV, Wp);

    dim3 gq(D_/128, M_/128, 3);           // fused QKV
    gemm_h<<<gq, 256, GH_BYTES>>>(nullptr, -1);

    dim3 ga(T_/128, H_, B_);              // (32, 12, 2)
    attn4<<<ga, 256, ASM_BYTES>>>();

    dim3 gp(D_/128, M_/128, 1);
    gemm_h<<<gp, 256, GH_BYTES>>>(out, 3);
}

// round 14
// speedup vs baseline: 2.5625x; 1.0790x over previous
#include <cuda_runtime.h>
#include <cuda_fp16.h>
#include <cstdint>

#define B_  2
#define T_  4096
#define D_  768
#define H_  12
#define DK_ 64
#define M_  (B_*T_)   // 8192

// Scratch (allocation-free): everything fp16 except final output
__device__ __half g_xh[M_*D_];
__device__ __half g_Wh[4][D_*D_];          // WQ, WK, WV, Wproj
__device__ __half g_Qh[B_*H_*T_*DK_];      // pre-scaled by 0.125*log2e
__device__ __half g_Kh[B_*H_*T_*DK_];
__device__ __half g_Vh[B_*H_*T_*DK_];
__device__ __half g_Oh[M_*D_];

__device__ __forceinline__ float ex2f(float x) {
    float y; asm("ex2.approx.f32 %0, %1;" : "=f"(y) : "f"(x)); return y;
}
__device__ __forceinline__ uint32_t packh2(float lo, float hi) {
    uint32_t r;
    asm("cvt.rn.f16x2.f32 %0, %1, %2;" : "=r"(r) : "f"(hi), "f"(lo));
    return r;
}
// exp2 of a score pair entirely in f16x2: pack, add(-m), ex2. Output IS the
// packed fp16 P fragment pair.
__device__ __forceinline__ uint32_t exp2h2(float s0, float s1, uint32_t negmn) {
    uint32_t d = packh2(s0, s1);
    asm("add.f16x2 %0, %0, %1;" : "+r"(d) : "r"(negmn));
    asm("ex2.approx.f16x2 %0, %0;" : "+r"(d));
    return d;
}
__device__ __forceinline__ void mma16(float* c, const uint32_t* a, const uint32_t* b) {
    asm volatile("mma.sync.aligned.m16n8k16.row.col.f32.f16.f16.f32 "
        "{%0,%1,%2,%3}, {%4,%5,%6,%7}, {%8,%9}, {%0,%1,%2,%3};"
        : "+f"(c[0]), "+f"(c[1]), "+f"(c[2]), "+f"(c[3])
        : "r"(a[0]), "r"(a[1]), "r"(a[2]), "r"(a[3]), "r"(b[0]), "r"(b[1]));
}
__device__ __forceinline__ void ldsm4(uint32_t* r, uint32_t addr) {
    asm volatile("ldmatrix.sync.aligned.m8n8.x4.shared.b16 {%0,%1,%2,%3}, [%4];"
        : "=r"(r[0]), "=r"(r[1]), "=r"(r[2]), "=r"(r[3]) : "r"(addr));
}
__device__ __forceinline__ void ldsm4t(uint32_t* r, uint32_t addr) {
    asm volatile("ldmatrix.sync.aligned.m8n8.x4.trans.shared.b16 {%0,%1,%2,%3}, [%4];"
        : "=r"(r[0]), "=r"(r[1]), "=r"(r[2]), "=r"(r[3]) : "r"(addr));
}
__device__ __forceinline__ void cpa16(uint32_t dst, const void* src) {
    asm volatile("cp.async.cg.shared.global [%0], [%1], 16;\n" :: "r"(dst), "l"(src));
}

#define QSC 0.180336881f   // 0.125 * log2(e)

// ===========================================================================
// One-shot fp32 -> fp16 conversion of x and the 4 weight matrices.
// ===========================================================================
__global__ void cvt_kernel(const float* __restrict__ x,
                           const float* __restrict__ wq, const float* __restrict__ wk,
                           const float* __restrict__ wv, const float* __restrict__ wp) {
    const int X4 = M_*D_/4;
    const int W4 = D_*D_/4;
    for (int i = blockIdx.x*blockDim.x + threadIdx.x; i < X4 + 4*W4;
         i += gridDim.x*blockDim.x) {
        const float* src; __half* dst; int off;
        if (i < X4) { src = x; dst = g_xh; off = i; }
        else {
            int j = i - X4, ws = j / W4; off = j - ws*W4;
            src = (ws == 0) ? wq : (ws == 1) ? wk : (ws == 2) ? wv : wp;
            dst = g_Wh[ws];
        }
        float4 v = ((const float4*)src)[off];
        uint2 u = { packh2(v.x, v.y), packh2(v.z, v.w) };
        *(uint2*)(dst + off*4) = u;
    }
}

// ===========================================================================
// fp16 GEMM (unchanged from R13 — proven): block 128x128, k-step 64, 256 thr.
// ===========================================================================
#define LA 72
#define LB 136
#define GH_BYTES ((2*128*LA + 2*64*LB) * 2)   // 71680

__global__ __launch_bounds__(256, 2) void gemm_h(float* __restrict__ Cf, int mode) {
    extern __shared__ __half shg[];
    __half* As = shg;                   // [2][128][72]
    __half* Ws = shg + 2*128*LA;        // [2][64][136]
    const int z = blockIdx.z;
    const __half* A = (mode == 3) ? g_Oh : g_xh;
    const __half* W = (mode == 3) ? g_Wh[3] : g_Wh[z];

    const int tid = threadIdx.x;
    const int w = tid >> 5, l = tid & 31, g = l >> 2, t = l & 3;
    const int wm = (w >> 2) * 64, wn = (w & 3) * 32;
    const int m0 = blockIdx.y * 128, n0 = blockIdx.x * 128;

    const uint32_t As_s = (uint32_t)__cvta_generic_to_shared(As);
    const uint32_t Ws_s = (uint32_t)__cvta_generic_to_shared(Ws);

    auto issue = [&](int ks, int buf) {
        #pragma unroll
        for (int j = 0; j < 4; j++) {
            int id = j*256 + tid;
            int m = id >> 3, c = (id & 7) * 8;
            cpa16(As_s + (uint32_t)(((buf*128 + m)*LA + c) * 2),
                  A + (size_t)(m0 + m)*D_ + ks*64 + c);
        }
        #pragma unroll
        for (int j = 0; j < 4; j++) {
            int id = j*256 + tid;
            int k = id >> 4, c = (id & 15) * 8;
            cpa16(Ws_s + (uint32_t)(((buf*64 + k)*LB + c) * 2),
                  W + (size_t)(ks*64 + k)*D_ + n0 + c);
        }
        asm volatile("cp.async.commit_group;\n");
    };

    const int arow = ((l >> 3) & 1)*8 + (l & 7);
    const int acol = ((l >> 4) & 1)*8;
    const int brow = ((l >> 3) & 1)*8 + (l & 7);
    const int bcol = ((l >> 4) & 1)*8;

    float acc[4][4][4] = {};
    issue(0, 0);
    for (int s = 0; s < 12; s++) {
        const int buf = s & 1;
        if (s + 1 < 12) {
            issue(s + 1, (s + 1) & 1);
            asm volatile("cp.async.wait_group 1;\n");
        } else {
            asm volatile("cp.async.wait_group 0;\n");
        }
        __syncthreads();

        const uint32_t Ab = As_s + (uint32_t)(buf*128*LA*2);
        const uint32_t Wb = Ws_s + (uint32_t)(buf*64*LB*2);
        #pragma unroll
        for (int kt = 0; kt < 4; kt++) {
            uint32_t bv[2][4];
            #pragma unroll
            for (int nt2 = 0; nt2 < 2; nt2++)
                ldsm4t(bv[nt2], Wb + (uint32_t)(((kt*16 + brow)*LB
                                   + wn + nt2*16 + bcol) * 2));
            #pragma unroll
            for (int mt = 0; mt < 4; mt++) {
                uint32_t a[4];
                ldsm4(a, Ab + (uint32_t)(((wm + mt*16 + arow)*LA
                                 + kt*16 + acol) * 2));
                #pragma unroll
                for (int nt2 = 0; nt2 < 2; nt2++) {
                    mma16(acc[mt][nt2*2],     a, bv[nt2]);
                    mma16(acc[mt][nt2*2 + 1], a, bv[nt2] + 2);
                }
            }
        }
        __syncthreads();
    }

    const float scl = (mode != 3 && z == 0) ? QSC : 1.f;
    #pragma unroll
    for (int mt = 0; mt < 4; mt++)
    #pragma unroll
    for (int hh = 0; hh < 2; hh++) {
        int m = m0 + wm + mt*16 + hh*8 + g;
        #pragma unroll
        for (int nt = 0; nt < 4; nt++) {
            int n = n0 + wn + nt*8 + 2*t;
            float c0 = acc[mt][nt][hh*2] * scl, c1 = acc[mt][nt][hh*2 + 1] * scl;
            if (mode == 3) {
                *(float2*)(Cf + (size_t)m*D_ + n) = make_float2(c0, c1);
            } else {
                __half* out = (z == 0) ? g_Qh : (z == 1) ? g_Kh : g_Vh;
                int h = n >> 6, dk = n & 63;
                int b = m >> 12, tt = m & 4095;
                *(uint32_t*)(out + ((size_t)(b*H_ + h)*T_ + tt)*DK_ + dk)
                    = packh2(c0, c1);
            }
        }
    }
}

// ===========================================================================
// Flash attention, fp16 m16n8k16, register-resident P.
// R14: f16x2 exp path (pack+add+ex2 per pair) and row-sum l accumulated as an
// extra tensor output via ones-MMA (no fp32 adds, no li shfl reductions).
// ===========================================================================
#define LH 72
#define ASM_BYTES ((128 + 2*64 + 2*64) * LH * 2)   // 55296

__global__ __launch_bounds__(256, 2) void attn4() {
    extern __shared__ __half sh[];
    __half* Qs = sh;                   // [128][72]
    __half* Ks = Qs + 128*LH;          // [2][64][72]
    __half* Vs = Ks + 2*64*LH;         // [2][64][72]

    const int qtile = blockIdx.x, h = blockIdx.y, b = blockIdx.z;
    const int tid = threadIdx.x;
    const int w = tid >> 5, l = tid & 31, g = l >> 2, t = l & 3;
    const int mw = w * 16;

    const __half* Qg = g_Qh + ((size_t)(b*H_ + h)*T_ + (size_t)qtile*128) * DK_;
    const __half* Kg = g_Kh + (size_t)(b*H_ + h)*T_ * DK_;
    const __half* Vg = g_Vh + (size_t)(b*H_ + h)*T_ * DK_;

    const uint32_t Qb = (uint32_t)__cvta_generic_to_shared(Qs);
    const uint32_t Kb = (uint32_t)__cvta_generic_to_shared(Ks);
    const uint32_t Vb = (uint32_t)__cvta_generic_to_shared(Vs);

    const int qrow = mw + ((l >> 3) & 1)*8 + (l & 7);
    const int qcol = ((l >> 4) & 1) * 8;
    const int krow = ((l >> 4) & 1)*8 + (l & 7);
    const int kcol = ((l >> 3) & 1) * 8;
    const int vrow = ((l >> 3) & 1)*8 + (l & 7);
    const int vcol = ((l >> 4) & 1) * 8;

    auto issueKV = [&](int it, int buf) {
        const __half* Ksrc = Kg + (size_t)it*64*DK_;
        const __half* Vsrc = Vg + (size_t)it*64*DK_;
        const uint32_t kb = Kb + (uint32_t)(buf*64*LH*2);
        const uint32_t vb = Vb + (uint32_t)(buf*64*LH*2);
        #pragma unroll
        for (int j = 0; j < 2; j++) {
            int id = j*256 + tid;
            int r = id >> 3, c = (id & 7) * 8;
            cpa16(kb + (uint32_t)((r*LH + c)*2), Ksrc + r*DK_ + c);
            cpa16(vb + (uint32_t)((r*LH + c)*2), Vsrc + r*DK_ + c);
        }
        asm volatile("cp.async.commit_group;\n");
    };

    #pragma unroll
    for (int j = 0; j < 4; j++) {
        int id = j*256 + tid;
        int r = id >> 3, c = (id & 7) * 8;
        cpa16(Qb + (uint32_t)((r*LH + c)*2), Qg + r*DK_ + c);
    }
    issueKV(0, 0);

    const uint32_t ones[2] = { 0x3C003C00u, 0x3C003C00u };  // fp16 1.0 x4

    float o[8][4] = {};
    float ls[4] = {};                      // row-sum accumulator (l), via mma
    float mi[2] = {-1e30f, -1e30f};

    for (int kv = 0; kv < T_/64; kv++) {
        const int buf = kv & 1;
        asm volatile("cp.async.wait_group 0;\n");
        __syncthreads();                   // data in; prev iter done
        if (kv + 1 < T_/64) issueKV(kv + 1, (kv + 1) & 1);

        const uint32_t Kbb = Kb + (uint32_t)(buf*64*LH*2);
        const uint32_t Vbb = Vb + (uint32_t)(buf*64*LH*2);

        // ---- S = Q @ K^T (log2 domain; QSC pre-folded into g_Qh) ----
        float s[8][4] = {};
        #pragma unroll
        for (int kt = 0; kt < 4; kt++) {
            uint32_t a[4];
            ldsm4(a, Qb + (uint32_t)((qrow*LH + kt*16 + qcol) * 2));
            #pragma unroll
            for (int nt2 = 0; nt2 < 4; nt2++) {
                uint32_t kr[4];
                ldsm4(kr, Kbb + (uint32_t)(((nt2*16 + krow)*LH + kt*16 + kcol) * 2));
                mma16(s[2*nt2],     a, kr);
                mma16(s[2*nt2 + 1], a, kr + 2);
            }
        }

        // ---- online softmax: max (fp32) then f16x2 exp ----
        float mx0 = -1e30f, mx1 = -1e30f;
        #pragma unroll
        for (int nt = 0; nt < 8; nt++) {
            mx0 = fmaxf(mx0, fmaxf(s[nt][0], s[nt][1]));
            mx1 = fmaxf(mx1, fmaxf(s[nt][2], s[nt][3]));
        }
        mx0 = fmaxf(mx0, __shfl_xor_sync(0xffffffffu, mx0, 1, 4));
        mx0 = fmaxf(mx0, __shfl_xor_sync(0xffffffffu, mx0, 2, 4));
        mx1 = fmaxf(mx1, __shfl_xor_sync(0xffffffffu, mx1, 1, 4));
        mx1 = fmaxf(mx1, __shfl_xor_sync(0xffffffffu, mx1, 2, 4));
        float mn0 = fmaxf(mi[0], mx0), mn1 = fmaxf(mi[1], mx1);
        float al0 = ex2f(mi[0] - mn0), al1 = ex2f(mi[1] - mn1);
        mi[0] = mn0; mi[1] = mn1;
        const uint32_t nm0 = packh2(-mn0, -mn0);
        const uint32_t nm1 = packh2(-mn1, -mn1);

        uint32_t ph[8][2];
        #pragma unroll
        for (int nt = 0; nt < 8; nt++) {
            ph[nt][0] = exp2h2(s[nt][0], s[nt][1], nm0);   // row g
            ph[nt][1] = exp2h2(s[nt][2], s[nt][3], nm1);   // row g+8
            o[nt][0] *= al0; o[nt][1] *= al0;
            o[nt][2] *= al1; o[nt][3] *= al1;
        }
        ls[0] *= al0; ls[1] *= al0; ls[2] *= al1; ls[3] *= al1;

        // ---- O += P @ V ; l += P @ ones (all on tensor pipe) ----
        #pragma unroll
        for (int kt = 0; kt < 4; kt++) {
            uint32_t pa[4] = { ph[2*kt][0], ph[2*kt][1],
                               ph[2*kt+1][0], ph[2*kt+1][1] };
            mma16(ls, pa, ones);
            #pragma unroll
            for (int nt2 = 0; nt2 < 4; nt2++) {
                uint32_t bv[4];
                ldsm4t(bv, Vbb + (uint32_t)(((kt*16 + vrow)*LH + nt2*16 + vcol) * 2));
                mma16(o[2*nt2],     pa, bv);
                mma16(o[2*nt2 + 1], pa, bv + 2);
            }
        }
    }

    // ---- normalize + write g_Oh (ls[0]=row g sum, ls[2]=row g+8 sum) ----
    float inv0 = 1.f / ls[0], inv1 = 1.f / ls[2];
    int r0 = qtile*128 + mw + g;
    __half* dst0 = g_Oh + ((size_t)b*T_ + r0    )*D_ + h*DK_;
    __half* dst1 = g_Oh + ((size_t)b*T_ + r0 + 8)*D_ + h*DK_;
    #pragma unroll
    for (int nt = 0; nt < 8; nt++) {
        *(uint32_t*)(dst0 + nt*8 + 2*t) = packh2(o[nt][0]*inv0, o[nt][1]*inv0);
        *(uint32_t*)(dst1 + nt*8 + 2*t) = packh2(o[nt][2]*inv1, o[nt][3]*inv1);
    }
}

// ===========================================================================
extern "C" void kernel_launch(void* const* d_in, const int* in_sizes, int n_in,
                              void* d_out, int out_size) {
    const float* x  = (const float*)d_in[0];
    const float* WQ = (const float*)d_in[1];
    const float* WK = (const float*)d_in[2];
    const float* WV = (const float*)d_in[3];
    const float* Wp = (const float*)d_in[4];
    float* out = (float*)d_out;

    cudaFuncSetAttribute(gemm_h, cudaFuncAttributeMaxDynamicSharedMemorySize,
                         GH_BYTES);
    cudaFuncSetAttribute(attn4, cudaFuncAttributeMaxDynamicSharedMemorySize,
                         ASM_BYTES);

    cvt_kernel<<<512, 256>>>(x, WQ, WK, WV, Wp);

    dim3 gq(D_/128, M_/128, 3);           // fused QKV
    gemm_h<<<gq, 256, GH_BYTES>>>(nullptr, -1);

    dim3 ga(T_/128, H_, B_);              // (32, 12, 2)
    attn4<<<ga, 256, ASM_BYTES>>>();

    dim3 gp(D_/128, M_/128, 1);
    gemm_h<<<gp, 256, GH_BYTES>>>(out, 3);
}